// round 1
// baseline (speedup 1.0000x reference)
#include <cuda_runtime.h>

#define S_LEN 4096
#define D_MODEL 256
#define QPB 8            // queries (=warps) per block
#define NTHREADS 256

__global__ __launch_bounds__(NTHREADS) void dwsa_kernel(
    const float2* __restrict__ x,   // [B, S, 2] as float2 (size, height)
    const float* __restrict__ Wq,   // [256]
    const float* __restrict__ Wk,   // [256]
    const float* __restrict__ Wv,   // [256]
    float* __restrict__ out)        // [B, S, 256]
{
    __shared__ float2 kv[S_LEN];    // 32 KB: (size, height) for this batch
    __shared__ float red[24];

    const int tid  = threadIdx.x;
    const int lane = tid & 31;
    const int warp = tid >> 5;
    const int blocks_per_batch = S_LEN / QPB;
    const int b  = blockIdx.x / blocks_per_batch;
    const int q0 = (blockIdx.x % blocks_per_batch) * QPB;

    // --- Stage batch (size, height) into smem; track h min/max for softmax bound ---
    const float2* xb = x + (size_t)b * S_LEN;
    float hmax = -1e30f, hmin = 1e30f;
    for (int i = tid; i < S_LEN; i += NTHREADS) {
        float2 v = xb[i];
        kv[i] = v;
        hmax = fmaxf(hmax, v.y);
        hmin = fminf(hmin, v.y);
    }
    // c = dot(Wq, Wk) / 16 ; NTHREADS == D_MODEL so one element per thread
    float cp = Wq[tid] * Wk[tid];
    #pragma unroll
    for (int o = 16; o > 0; o >>= 1) {
        hmax = fmaxf(hmax, __shfl_xor_sync(0xffffffffu, hmax, o));
        hmin = fminf(hmin, __shfl_xor_sync(0xffffffffu, hmin, o));
        cp  += __shfl_xor_sync(0xffffffffu, cp, o);
    }
    if (lane == 0) { red[warp] = hmax; red[8 + warp] = hmin; red[16 + warp] = cp; }
    __syncthreads();
    hmax = red[0]; hmin = red[8];
    float csum = red[16];
    #pragma unroll
    for (int w = 1; w < 8; w++) {
        hmax = fmaxf(hmax, red[w]);
        hmin = fminf(hmin, red[8 + w]);
        csum += red[16 + w];
    }
    const float c = csum * (1.0f / 16.0f);

    // --- This warp's query ---
    const int s = q0 + warp;
    const float2 sv = kv[s];              // broadcast LDS
    const float LOG2E = 1.4426950408889634f;
    const float a2    = c * sv.y * LOG2E;           // log2-domain h coefficient
    const float nlam2 = -0.5f * LOG2E;              // -lambda in log2 domain
    const float nM2   = -fmaxf(a2 * hmax, a2 * hmin); // -upper bound of a2*h_t
    const float szs   = sv.x;

    // --- Pairwise loop: each lane covers t = lane, lane+32, ... (128 t's) ---
    float z0 = 0.f, z1 = 0.f, z2 = 0.f, z3 = 0.f;
    float r0 = 0.f, r1 = 0.f, r2 = 0.f, r3 = 0.f;
    #pragma unroll 4
    for (int t = lane; t < S_LEN; t += 128) {
        float2 e0 = kv[t];
        float2 e1 = kv[t + 32];
        float2 e2 = kv[t + 64];
        float2 e3 = kv[t + 96];
        float p0 = exp2f(fmaf(a2, e0.y, fmaf(nlam2, fabsf(szs - e0.x), nM2)));
        float p1 = exp2f(fmaf(a2, e1.y, fmaf(nlam2, fabsf(szs - e1.x), nM2)));
        float p2 = exp2f(fmaf(a2, e2.y, fmaf(nlam2, fabsf(szs - e2.x), nM2)));
        float p3 = exp2f(fmaf(a2, e3.y, fmaf(nlam2, fabsf(szs - e3.x), nM2)));
        if (e0.y == 0.f) p0 = 0.f;   // key mask (exact-zero height)
        if (e1.y == 0.f) p1 = 0.f;
        if (e2.y == 0.f) p2 = 0.f;
        if (e3.y == 0.f) p3 = 0.f;
        z0 += p0; r0 = fmaf(p0, e0.y, r0);
        z1 += p1; r1 = fmaf(p1, e1.y, r1);
        z2 += p2; r2 = fmaf(p2, e2.y, r2);
        z3 += p3; r3 = fmaf(p3, e3.y, r3);
    }
    float z = (z0 + z1) + (z2 + z3);
    float r = (r0 + r1) + (r2 + r3);
    #pragma unroll
    for (int o = 16; o > 0; o >>= 1) {
        z += __shfl_xor_sync(0xffffffffu, z, o);
        r += __shfl_xor_sync(0xffffffffu, r, o);
    }
    const float rv = (z > 0.f) ? __fdividef(r, z) : 0.f;

    // --- out[b,s,:] = rv * Wv ---
    const float4* wv4 = (const float4*)Wv;
    float4* o4 = (float4*)(out + ((size_t)b * S_LEN + s) * D_MODEL);
    #pragma unroll
    for (int k = 0; k < 2; k++) {
        float4 w = wv4[lane * 2 + k];
        o4[lane * 2 + k] = make_float4(rv * w.x, rv * w.y, rv * w.z, rv * w.w);
    }
}

extern "C" void kernel_launch(void* const* d_in, const int* in_sizes, int n_in,
                              void* d_out, int out_size) {
    const float2* x  = (const float2*)d_in[0];
    const float*  Wq = (const float*)d_in[1];
    const float*  Wk = (const float*)d_in[2];
    const float*  Wv = (const float*)d_in[3];
    float* out = (float*)d_out;

    const int B = in_sizes[0] / (S_LEN * 2);
    const int grid = B * (S_LEN / QPB);
    dwsa_kernel<<<grid, NTHREADS>>>(x, Wq, Wk, Wv, out);
}

// round 2
// speedup vs baseline: 1.1494x; 1.1494x over previous
#include <cuda_runtime.h>

#define S_LEN 4096
#define D_MODEL 256
#define QPB 8            // queries (=warps) per block
#define NTHREADS 256

typedef unsigned long long ull;

__device__ __forceinline__ ull pk2(float lo, float hi) {
    ull r; asm("mov.b64 %0,{%1,%2};" : "=l"(r) : "f"(lo), "f"(hi)); return r;
}
__device__ __forceinline__ void upk2(ull a, float& lo, float& hi) {
    asm("mov.b64 {%0,%1},%2;" : "=f"(lo), "=f"(hi) : "l"(a));
}
__device__ __forceinline__ ull add2(ull a, ull b) {
    ull r; asm("add.rn.f32x2 %0,%1,%2;" : "=l"(r) : "l"(a), "l"(b)); return r;
}
__device__ __forceinline__ ull fma2(ull a, ull b, ull c) {
    ull r; asm("fma.rn.f32x2 %0,%1,%2,%3;" : "=l"(r) : "l"(a), "l"(b), "l"(c)); return r;
}
__device__ __forceinline__ ull ex22(ull a) {
    ull r;
    asm("{\n\t.reg .f32 al,ah,rl,rh;\n\t"
        "mov.b64 {al,ah},%1;\n\t"
        "ex2.approx.f32 rl,al;\n\t"
        "ex2.approx.f32 rh,ah;\n\t"
        "mov.b64 %0,{rl,rh};\n\t}" : "=l"(r) : "l"(a));
    return r;
}

__global__ __launch_bounds__(NTHREADS) void dwsa_kernel(
    const float2* __restrict__ x,   // [B, S, 2] (size, height)
    const float* __restrict__ Wq,
    const float* __restrict__ Wk,
    const float* __restrict__ Wv,
    float* __restrict__ out)        // [B, S, 256]
{
    __shared__ float ksz[S_LEN];    // -lambda2 * size  (16 KB)
    __shared__ float kh [S_LEN];    // height           (16 KB)
    __shared__ float red[24];

    const int tid  = threadIdx.x;
    const int lane = tid & 31;
    const int warp = tid >> 5;
    const int blocks_per_batch = S_LEN / QPB;
    const int b  = blockIdx.x / blocks_per_batch;
    const int q0 = (blockIdx.x % blocks_per_batch) * QPB;

    const float LOG2E = 1.4426950408889634f;
    const float LAM2  = 0.5f * LOG2E;   // lambda in log2 domain

    // --- Stage batch into SoA smem; track h min/max; detect exact zeros ---
    const float2* xb = x + (size_t)b * S_LEN;
    float hmax = -1e30f, hmin = 1e30f;
    int zflag = 0;
    for (int i = tid; i < S_LEN; i += NTHREADS) {
        float2 v = xb[i];
        ksz[i] = -LAM2 * v.x;
        kh[i]  = v.y;
        hmax = fmaxf(hmax, v.y);
        hmin = fminf(hmin, v.y);
        zflag |= (v.y == 0.0f);
    }
    // c = dot(Wq, Wk) / 16 ; NTHREADS == D_MODEL
    float cp = Wq[tid] * Wk[tid];
    #pragma unroll
    for (int o = 16; o > 0; o >>= 1) {
        hmax = fmaxf(hmax, __shfl_xor_sync(0xffffffffu, hmax, o));
        hmin = fminf(hmin, __shfl_xor_sync(0xffffffffu, hmin, o));
        cp  += __shfl_xor_sync(0xffffffffu, cp, o);
    }
    if (lane == 0) { red[warp] = hmax; red[8 + warp] = hmin; red[16 + warp] = cp; }
    const int anyzero = __syncthreads_or(zflag);
    hmax = red[0]; hmin = red[8];
    float csum = red[16];
    #pragma unroll
    for (int w = 1; w < 8; w++) {
        hmax = fmaxf(hmax, red[w]);
        hmin = fminf(hmin, red[8 + w]);
        csum += red[16 + w];
    }
    const float c = csum * (1.0f / 16.0f);

    // --- This warp's query ---
    const int s = q0 + warp;
    const float qsz = -ksz[s];            // +lambda2 * size_s
    const float hs  = kh[s];
    const float a2  = c * hs * LOG2E;
    const float nM2 = -fmaxf(a2 * hmax, a2 * hmin);

    float z, r;
    if (!anyzero) {
        // ===== Fast path: packed f32x2, no mask =====
        const ull qsz2 = pk2(qsz, qsz);
        const ull a2p  = pk2(a2, a2);
        const ull nM2p = pk2(nM2, nM2);
        const ull SGN  = 0x8000000080000000ULL;
        const float4* ksz4 = (const float4*)ksz;
        const float4* kh4  = (const float4*)kh;

        ull z01 = 0, z23 = 0, r01 = 0, r23 = 0;   // 0x0 == packed (0.f, 0.f)
        #pragma unroll 4
        for (int ch = 0; ch < S_LEN / 128; ch++) {
            const int idx = lane + ch * 32;
            float4 s4 = ksz4[idx];
            float4 h4 = kh4[idx];
            ull h01 = pk2(h4.x, h4.y);
            ull h23 = pk2(h4.z, h4.w);
            ull u01 = add2(qsz2, pk2(s4.x, s4.y)) | SGN;   // -lam2*|dsz|
            ull u23 = add2(qsz2, pk2(s4.z, s4.w)) | SGN;
            ull t01 = fma2(a2p, h01, nM2p);
            ull t23 = fma2(a2p, h23, nM2p);
            ull p01 = ex22(add2(t01, u01));
            ull p23 = ex22(add2(t23, u23));
            z01 = add2(z01, p01);
            z23 = add2(z23, p23);
            r01 = fma2(p01, h01, r01);
            r23 = fma2(p23, h23, r23);
        }
        float za, zb, zc, zd, ra, rb, rc, rd;
        upk2(z01, za, zb); upk2(z23, zc, zd);
        upk2(r01, ra, rb); upk2(r23, rc, rd);
        z = (za + zb) + (zc + zd);
        r = (ra + rb) + (rc + rd);
    } else {
        // ===== Masked fallback (rare): scalar with key mask =====
        float zz = 0.f, rr = 0.f;
        for (int t = lane; t < S_LEN; t += 32) {
            float ht = kh[t];
            float p = exp2f(fmaf(a2, ht, (qsz + ksz[t] >= 0.f ? -(qsz + ksz[t]) : (qsz + ksz[t])) + nM2));
            if (ht == 0.f) p = 0.f;
            zz += p; rr = fmaf(p, ht, rr);
        }
        z = zz; r = rr;
    }

    #pragma unroll
    for (int o = 16; o > 0; o >>= 1) {
        z += __shfl_xor_sync(0xffffffffu, z, o);
        r += __shfl_xor_sync(0xffffffffu, r, o);
    }
    const float rv = (z > 0.f) ? __fdividef(r, z) : 0.f;

    // --- out[b,s,:] = rv * Wv ---
    const float4* wv4 = (const float4*)Wv;
    float4* o4 = (float4*)(out + ((size_t)b * S_LEN + s) * D_MODEL);
    #pragma unroll
    for (int k = 0; k < 2; k++) {
        float4 w = wv4[lane * 2 + k];
        o4[lane * 2 + k] = make_float4(rv * w.x, rv * w.y, rv * w.z, rv * w.w);
    }
}

extern "C" void kernel_launch(void* const* d_in, const int* in_sizes, int n_in,
                              void* d_out, int out_size) {
    const float2* x  = (const float2*)d_in[0];
    const float*  Wq = (const float*)d_in[1];
    const float*  Wk = (const float*)d_in[2];
    const float*  Wv = (const float*)d_in[3];
    float* out = (float*)d_out;

    const int B = in_sizes[0] / (S_LEN * 2);
    const int grid = B * (S_LEN / QPB);
    dwsa_kernel<<<grid, NTHREADS>>>(x, Wq, Wk, Wv, out);
}

// round 3
// speedup vs baseline: 1.2139x; 1.0561x over previous
#include <cuda_runtime.h>
#include <cstdint>

#define S_LEN 4096
#define D_MODEL 256
#define QPW 2                 // queries per warp (sequential)
#define QPB (8 * QPW)         // 16 queries per block
#define NTHREADS 256

typedef unsigned long long ull;

__device__ __forceinline__ ull pk2(float lo, float hi) {
    ull r; asm("mov.b64 %0,{%1,%2};" : "=l"(r) : "f"(lo), "f"(hi)); return r;
}
__device__ __forceinline__ void upk2(ull a, float& lo, float& hi) {
    asm("mov.b64 {%0,%1},%2;" : "=f"(lo), "=f"(hi) : "l"(a));
}
__device__ __forceinline__ ull add2(ull a, ull b) {
    ull r; asm("add.rn.f32x2 %0,%1,%2;" : "=l"(r) : "l"(a), "l"(b)); return r;
}
__device__ __forceinline__ ull fma2(ull a, ull b, ull c) {
    ull r; asm("fma.rn.f32x2 %0,%1,%2,%3;" : "=l"(r) : "l"(a), "l"(b), "l"(c)); return r;
}
__device__ __forceinline__ ull ex22(ull a) {
    ull r;
    asm("{\n\t.reg .f32 al,ah,rl,rh;\n\t"
        "mov.b64 {al,ah},%1;\n\t"
        "ex2.approx.f32 rl,al;\n\t"
        "ex2.approx.f32 rh,ah;\n\t"
        "mov.b64 %0,{rl,rh};\n\t}" : "=l"(r) : "l"(a));
    return r;
}
// 16B shared load born as two packed b64 registers — no pack MOVs.
__device__ __forceinline__ void lds2(ull& a, ull& b, uint32_t addr) {
    asm volatile("ld.shared.v2.u64 {%0,%1},[%2];" : "=l"(a), "=l"(b) : "r"(addr));
}

// One query's full key sweep. Returns rv = (sum p*h) / (sum p).
__device__ __forceinline__ float query_sweep(uint32_t nsz_a, uint32_t h_a,
                                             float qsz, float a2, float nM2)
{
    const ull qsz2 = pk2(qsz, qsz);
    const ull a2p  = pk2(a2, a2);
    const ull nM2p = pk2(nM2, nM2);
    const ull SGN  = 0x8000000080000000ULL;

    ull z01 = 0, z23 = 0, r01 = 0, r23 = 0;
    #pragma unroll 4
    for (int ch = 0; ch < S_LEN / 128; ch++) {
        ull s01, s23, h01, h23;
        lds2(s01, s23, nsz_a + ch * 512);
        lds2(h01, h23, h_a  + ch * 512);
        ull u01 = add2(qsz2, s01) | SGN;   // -lam2*|dsz| (packed, 2 LOP3)
        ull u23 = add2(qsz2, s23) | SGN;
        ull p01 = ex22(add2(fma2(a2p, h01, nM2p), u01));
        ull p23 = ex22(add2(fma2(a2p, h23, nM2p), u23));
        z01 = add2(z01, p01);
        z23 = add2(z23, p23);
        r01 = fma2(p01, h01, r01);
        r23 = fma2(p23, h23, r23);
    }
    float za, zb, zc, zd, ra, rb, rc, rd;
    upk2(z01, za, zb); upk2(z23, zc, zd);
    upk2(r01, ra, rb); upk2(r23, rc, rd);
    float z = (za + zb) + (zc + zd);
    float r = (ra + rb) + (rc + rd);
    #pragma unroll
    for (int o = 16; o > 0; o >>= 1) {
        z += __shfl_xor_sync(0xffffffffu, z, o);
        r += __shfl_xor_sync(0xffffffffu, r, o);
    }
    return (z > 0.f) ? __fdividef(r, z) : 0.f;
}

__global__ __launch_bounds__(NTHREADS) void dwsa_kernel(
    const float2* __restrict__ x,   // [B, S, 2] (size, height)
    const float* __restrict__ Wq,
    const float* __restrict__ Wk,
    const float* __restrict__ Wv,
    float* __restrict__ out)        // [B, S, 256]
{
    __shared__ float nsz[S_LEN];    // -lam2 * size  (16 KB)
    __shared__ float hh [S_LEN];    // height        (16 KB)
    __shared__ float red[24];

    const int tid  = threadIdx.x;
    const int lane = tid & 31;
    const int warp = tid >> 5;
    const int blocks_per_batch = S_LEN / QPB;
    const int b  = blockIdx.x / blocks_per_batch;
    const int q0 = (blockIdx.x % blocks_per_batch) * QPB;

    const float LOG2E = 1.4426950408889634f;
    const float LAM2  = 0.5f * LOG2E;

    // --- Stage batch (SoA), track h min/max, detect exact-zero heights ---
    const float2* xb = x + (size_t)b * S_LEN;
    float hmax = -1e30f, hmin = 1e30f;
    int zflag = 0;
    for (int i = tid; i < S_LEN; i += NTHREADS) {
        float2 v = xb[i];
        nsz[i] = -LAM2 * v.x;
        hh[i]  = v.y;
        hmax = fmaxf(hmax, v.y);
        hmin = fminf(hmin, v.y);
        zflag |= (v.y == 0.0f);
    }
    float cp = Wq[tid] * Wk[tid];           // NTHREADS == D_MODEL
    #pragma unroll
    for (int o = 16; o > 0; o >>= 1) {
        hmax = fmaxf(hmax, __shfl_xor_sync(0xffffffffu, hmax, o));
        hmin = fminf(hmin, __shfl_xor_sync(0xffffffffu, hmin, o));
        cp  += __shfl_xor_sync(0xffffffffu, cp, o);
    }
    if (lane == 0) { red[warp] = hmax; red[8 + warp] = hmin; red[16 + warp] = cp; }
    const int anyzero = __syncthreads_or(zflag);
    hmax = red[0]; hmin = red[8];
    float csum = red[16];
    #pragma unroll
    for (int w = 1; w < 8; w++) {
        hmax = fmaxf(hmax, red[w]);
        hmin = fminf(hmin, red[8 + w]);
        csum += red[16 + w];
    }
    const float c = csum * (1.0f / 16.0f);

    const uint32_t nsz_a = (uint32_t)__cvta_generic_to_shared(nsz) + lane * 16;
    const uint32_t h_a   = (uint32_t)__cvta_generic_to_shared(hh)  + lane * 16;
    const float4* wv4 = (const float4*)Wv;

    #pragma unroll
    for (int qi = 0; qi < QPW; qi++) {
        const int s = q0 + warp + qi * 8;
        const float qsz = -nsz[s];                 // +lam2 * size_s (broadcast LDS)
        const float hs  = hh[s];
        const float a2  = c * hs * LOG2E;
        const float nM2 = -fmaxf(a2 * hmax, a2 * hmin);

        float rv;
        if (!anyzero) {
            rv = query_sweep(nsz_a, h_a, qsz, a2, nM2);
        } else {
            // Masked fallback (rare): scalar with key mask
            float zz = 0.f, rr = 0.f;
            for (int t = lane; t < S_LEN; t += 32) {
                float ht = hh[t];
                float d  = qsz + nsz[t];
                float p  = exp2f(fmaf(a2, ht, -fabsf(d) + nM2));
                if (ht == 0.f) p = 0.f;
                zz += p; rr = fmaf(p, ht, rr);
            }
            #pragma unroll
            for (int o = 16; o > 0; o >>= 1) {
                zz += __shfl_xor_sync(0xffffffffu, zz, o);
                rr += __shfl_xor_sync(0xffffffffu, rr, o);
            }
            rv = (zz > 0.f) ? __fdividef(rr, zz) : 0.f;
        }

        float4* o4 = (float4*)(out + ((size_t)b * S_LEN + s) * D_MODEL);
        #pragma unroll
        for (int k = 0; k < 2; k++) {
            float4 w = wv4[lane * 2 + k];
            o4[lane * 2 + k] = make_float4(rv * w.x, rv * w.y, rv * w.z, rv * w.w);
        }
    }
}

extern "C" void kernel_launch(void* const* d_in, const int* in_sizes, int n_in,
                              void* d_out, int out_size) {
    const float2* x  = (const float2*)d_in[0];
    const float*  Wq = (const float*)d_in[1];
    const float*  Wk = (const float*)d_in[2];
    const float*  Wv = (const float*)d_in[3];
    float* out = (float*)d_out;

    const int B = in_sizes[0] / (S_LEN * 2);
    const int grid = B * (S_LEN / QPB);
    dwsa_kernel<<<grid, NTHREADS>>>(x, Wq, Wk, Wv, out);
}

// round 4
// speedup vs baseline: 1.3269x; 1.0931x over previous
#include <cuda_runtime.h>
#include <cstdint>

#define S_LEN 4096
#define D_MODEL 256
#define QPW 2                 // queries per warp, interleaved in one sweep
#define QPB (8 * QPW)         // 16 queries per block
#define NTHREADS 256

typedef unsigned long long ull;

__device__ __forceinline__ ull pk2(float lo, float hi) {
    ull r; asm("mov.b64 %0,{%1,%2};" : "=l"(r) : "f"(lo), "f"(hi)); return r;
}
__device__ __forceinline__ void splt(ull a, float& lo, float& hi) {
    asm("mov.b64 {%0,%1},%2;" : "=f"(lo), "=f"(hi) : "l"(a));
}
__device__ __forceinline__ ull add2(ull a, ull b) {
    ull r; asm("add.rn.f32x2 %0,%1,%2;" : "=l"(r) : "l"(a), "l"(b)); return r;
}
__device__ __forceinline__ ull fma2(ull a, ull b, ull c) {
    ull r; asm("fma.rn.f32x2 %0,%1,%2,%3;" : "=l"(r) : "l"(a), "l"(b), "l"(c)); return r;
}
__device__ __forceinline__ float ex2f(float a) {
    float r; asm("ex2.approx.f32 %0,%1;" : "=f"(r) : "f"(a)); return r;
}
__device__ __forceinline__ void lds2(ull& a, ull& b, uint32_t addr) {
    asm volatile("ld.shared.v2.u64 {%0,%1},[%2];" : "=l"(a), "=l"(b) : "r"(addr));
}

#define SGNM 0x8000000080000000ULL

// Packed front-end, scalar back-end. Splits only — no scalar->pair joins.
__device__ __forceinline__ void proc2(ull s, ull h, ull qsz2, ull a2p, ull nM2p,
                                      float& za, float& zb, float& ra, float& rb)
{
    ull u   = add2(qsz2, s) | SGNM;       // -(lam2*|dsz|), 2x LOP3 (alu)
    ull t   = fma2(a2p, h, nM2p);
    ull arg = add2(t, u);
    float a0, a1, h0, h1;
    splt(arg, a0, a1);
    splt(h,   h0, h1);
    float p0 = ex2f(a0);
    float p1 = ex2f(a1);
    za += p0;  zb += p1;
    ra = fmaf(p0, h0, ra);
    rb = fmaf(p1, h1, rb);
}

__global__ __launch_bounds__(NTHREADS) void dwsa_kernel(
    const float2* __restrict__ x,   // [B, S, 2] (size, height)
    const float* __restrict__ Wq,
    const float* __restrict__ Wk,
    const float* __restrict__ Wv,
    float* __restrict__ out)        // [B, S, 256]
{
    __shared__ float nsz[S_LEN];    // -lam2 * size  (16 KB)
    __shared__ float hh [S_LEN];    // height        (16 KB)
    __shared__ float red[24];

    const int tid  = threadIdx.x;
    const int lane = tid & 31;
    const int warp = tid >> 5;
    const int blocks_per_batch = S_LEN / QPB;
    const int b  = blockIdx.x / blocks_per_batch;
    const int q0 = (blockIdx.x % blocks_per_batch) * QPB;

    const float LOG2E = 1.4426950408889634f;
    const float LAM2  = 0.5f * LOG2E;

    // --- Stage batch (SoA), track h min/max, detect exact-zero heights ---
    const float2* xb = x + (size_t)b * S_LEN;
    float hmax = -1e30f, hmin = 1e30f;
    int zflag = 0;
    for (int i = tid; i < S_LEN; i += NTHREADS) {
        float2 v = xb[i];
        nsz[i] = -LAM2 * v.x;
        hh[i]  = v.y;
        hmax = fmaxf(hmax, v.y);
        hmin = fminf(hmin, v.y);
        zflag |= (v.y == 0.0f);
    }
    float cp = Wq[tid] * Wk[tid];           // NTHREADS == D_MODEL
    #pragma unroll
    for (int o = 16; o > 0; o >>= 1) {
        hmax = fmaxf(hmax, __shfl_xor_sync(0xffffffffu, hmax, o));
        hmin = fminf(hmin, __shfl_xor_sync(0xffffffffu, hmin, o));
        cp  += __shfl_xor_sync(0xffffffffu, cp, o);
    }
    if (lane == 0) { red[warp] = hmax; red[8 + warp] = hmin; red[16 + warp] = cp; }
    const int anyzero = __syncthreads_or(zflag);
    hmax = red[0]; hmin = red[8];
    float csum = red[16];
    #pragma unroll
    for (int w = 1; w < 8; w++) {
        hmax = fmaxf(hmax, red[w]);
        hmin = fminf(hmin, red[8 + w]);
        csum += red[16 + w];
    }
    const float c = csum * (1.0f / 16.0f);

    // --- Two queries per warp, interleaved over one key sweep ---
    const int sA = q0 + warp;
    const int sB = q0 + warp + 8;
    const float qszA = -nsz[sA], hsA = hh[sA];
    const float qszB = -nsz[sB], hsB = hh[sB];
    const float a2A  = c * hsA * LOG2E;
    const float a2B  = c * hsB * LOG2E;
    const float nM2A = -fmaxf(a2A * hmax, a2A * hmin);
    const float nM2B = -fmaxf(a2B * hmax, a2B * hmin);

    float zv[QPW], rv[QPW];

    if (!anyzero) {
        const ull qszA2 = pk2(qszA, qszA), a2Ap = pk2(a2A, a2A), nM2Ap = pk2(nM2A, nM2A);
        const ull qszB2 = pk2(qszB, qszB), a2Bp = pk2(a2B, a2B), nM2Bp = pk2(nM2B, nM2B);
        const uint32_t nsz_a = (uint32_t)__cvta_generic_to_shared(nsz) + lane * 16;
        const uint32_t h_a   = (uint32_t)__cvta_generic_to_shared(hh)  + lane * 16;

        float zA0 = 0.f, zA1 = 0.f, rA0 = 0.f, rA1 = 0.f;
        float zB0 = 0.f, zB1 = 0.f, rB0 = 0.f, rB1 = 0.f;

        #pragma unroll 2
        for (int ch = 0; ch < S_LEN / 128; ch++) {
            ull s01, s23, h01, h23;
            lds2(s01, s23, nsz_a + ch * 512);
            lds2(h01, h23, h_a  + ch * 512);
            proc2(s01, h01, qszA2, a2Ap, nM2Ap, zA0, zA1, rA0, rA1);
            proc2(s23, h23, qszA2, a2Ap, nM2Ap, zA0, zA1, rA0, rA1);
            proc2(s01, h01, qszB2, a2Bp, nM2Bp, zB0, zB1, rB0, rB1);
            proc2(s23, h23, qszB2, a2Bp, nM2Bp, zB0, zB1, rB0, rB1);
        }
        zv[0] = zA0 + zA1;  rv[0] = rA0 + rA1;
        zv[1] = zB0 + zB1;  rv[1] = rB0 + rB1;
    } else {
        // Masked fallback (rare): scalar with key mask
        #pragma unroll
        for (int qi = 0; qi < QPW; qi++) {
            const float qsz = qi ? qszB : qszA;
            const float a2  = qi ? a2B  : a2A;
            const float nM2 = qi ? nM2B : nM2A;
            float zz = 0.f, rr = 0.f;
            for (int t = lane; t < S_LEN; t += 32) {
                float ht = hh[t];
                float d  = qsz + nsz[t];
                float p  = exp2f(fmaf(a2, ht, -fabsf(d) + nM2));
                if (ht == 0.f) p = 0.f;
                zz += p; rr = fmaf(p, ht, rr);
            }
            zv[qi] = zz; rv[qi] = rr;
        }
    }

    const float4* wv4 = (const float4*)Wv;
    #pragma unroll
    for (int qi = 0; qi < QPW; qi++) {
        float z = zv[qi], r = rv[qi];
        #pragma unroll
        for (int o = 16; o > 0; o >>= 1) {
            z += __shfl_xor_sync(0xffffffffu, z, o);
            r += __shfl_xor_sync(0xffffffffu, r, o);
        }
        const float val = (z > 0.f) ? __fdividef(r, z) : 0.f;
        const int s = q0 + warp + qi * 8;
        float4* o4 = (float4*)(out + ((size_t)b * S_LEN + s) * D_MODEL);
        #pragma unroll
        for (int k = 0; k < 2; k++) {
            float4 w = wv4[lane * 2 + k];
            o4[lane * 2 + k] = make_float4(val * w.x, val * w.y, val * w.z, val * w.w);
        }
    }
}

extern "C" void kernel_launch(void* const* d_in, const int* in_sizes, int n_in,
                              void* d_out, int out_size) {
    const float2* x  = (const float2*)d_in[0];
    const float*  Wq = (const float*)d_in[1];
    const float*  Wk = (const float*)d_in[2];
    const float*  Wv = (const float*)d_in[3];
    float* out = (float*)d_out;

    const int B = in_sizes[0] / (S_LEN * 2);
    const int grid = B * (S_LEN / QPB);
    dwsa_kernel<<<grid, NTHREADS>>>(x, Wq, Wk, Wv, out);
}